// round 14
// baseline (speedup 1.0000x reference)
#include <cuda_runtime.h>
#include <stdint.h>

// ProbabilisticPatching: Gumbel-top-k, exact JAX *partitionable* threefry stream
// x:[2048,512] f32, weights:[64,512] f32, rng_seed int -> out [2048,64,1024] f32
//
// element i: (o0,o1)=threefry2x32((0,seed),(0,i)); bits=o0^o1
// u = max(1e-20, ((bits>>9)|0x3F800000).f32 - 1 + 1e-20)
// exact score = log_softmax(w)[p,f] - logf(-logf(u)); top-32 per (b,p) row.
//
// Fast path: approx score a (|a-s| <= ~4.3e-5), ONE 256-bin LINEAR histogram
// over score space; elements outside bin +/- EPS are provably IN/OUT; the
// band recomputes the bit-exact reference score (incl. index tie-break).
// R9/R10: threefry serial dep chain -> keep SHF+LOP3. R12: don't cap regs.
// R14: all warps redundantly scan the histogram (reduce_max broadcast) ->
// one fewer __syncthreads and no 3-warps-idle scan window.

#define BATCH   2048
#define NP      64
#define NF      512
#define PL      32
#define NROWS   (BATCH * NP)          // 131072
#define TPB     128                   // threads per block
#define EPT     4                     // elements per thread (NF / TPB)
#define EPSB    2e-4f                 // band half-width (> 2x approx error bound)

__device__ float g_logp[NP * NF];

// ---------------- threefry2x32 (20 rounds, Skein schedule) ----------------
__device__ __forceinline__ void tf_round(uint32_t& a, uint32_t& b, int r) {
    a += b;
    b = __funnelshift_l(b, b, r);   // rotl
    b ^= a;
}

__device__ __forceinline__ void threefry2x32(uint32_t k0, uint32_t k1,
                                             uint32_t c0, uint32_t c1,
                                             uint32_t& o0, uint32_t& o1) {
    uint32_t ks2 = k0 ^ k1 ^ 0x1BD11BDAu;
    uint32_t x0 = c0 + k0, x1 = c1 + k1;
    tf_round(x0, x1, 13); tf_round(x0, x1, 15); tf_round(x0, x1, 26); tf_round(x0, x1, 6);
    x0 += k1;  x1 += ks2 + 1u;
    tf_round(x0, x1, 17); tf_round(x0, x1, 29); tf_round(x0, x1, 16); tf_round(x0, x1, 24);
    x0 += ks2; x1 += k0 + 2u;
    tf_round(x0, x1, 13); tf_round(x0, x1, 15); tf_round(x0, x1, 26); tf_round(x0, x1, 6);
    x0 += k0;  x1 += k1 + 3u;
    tf_round(x0, x1, 17); tf_round(x0, x1, 29); tf_round(x0, x1, 16); tf_round(x0, x1, 24);
    x0 += k1;  x1 += ks2 + 4u;
    tf_round(x0, x1, 13); tf_round(x0, x1, 15); tf_round(x0, x1, 26); tf_round(x0, x1, 6);
    x0 += ks2; x1 += k0 + 5u;
    o0 = x0; o1 = x1;
}

// JAX uniform(minval=1e-20, maxval=1.0), f32 path (exact reference form)
__device__ __forceinline__ float bits_to_uniform(uint32_t b) {
    float f = __uint_as_float((b >> 9) | 0x3F800000u) - 1.0f; // [0,1)
    return fmaxf(f + 1e-20f, 1e-20f);
}

// order-preserving float -> uint (only used for band exact-key packing)
__device__ __forceinline__ uint32_t ford(float f) {
    uint32_t u = __float_as_uint(f);
    return (u & 0x80000000u) ? ~u : (u | 0x80000000u);
}

// approx score: lp - log(-log(u)), |err| <= ~4.3e-5 absolute; branchless
// NOTE: fmaxf(ff,1e-20f) == fmaxf(ff+1e-20f,1e-20f) bitwise (1e-20 < ulp/2)
__device__ __forceinline__ float approx_score(uint32_t bits, float lp) {
    float ff = __uint_as_float((bits >> 9) | 0x3F800000u) - 1.0f;  // [0,1), exact
    float u  = fmaxf(ff, 1e-20f);
    // path 1: u in [0.875,1): inner = -log1p(d), d = ff-1 exact, deg-4 Taylor
    // truncation rel err <= |d|^4/6 = 4.1e-5 at d = -0.125
    float d = ff - 1.0f;
    float P = fmaf(d, 0.2f, -0.25f);
    P = fmaf(d, P,  1.0f/3.0f);
    P = fmaf(d, P, -0.5f);
    P = fmaf(d, P,  1.0f);
    float inner_hi = -d * P;
    // path 2: u < 0.875: |log u| >= 0.1335, MUFU relative error is fine
    float inner_lo = -__logf(u);
    float inner = (ff >= 0.875f) ? inner_hi : inner_lo;
    return lp - __logf(inner);
}

// exact score: bit-identical to the reference path (R3/R4)
__device__ __forceinline__ float exact_score(uint32_t bits, float lp) {
    return lp - logf(-logf(bits_to_uniform(bits)));
}

// ---------------- kernel A: logp = log_softmax(weights, axis=-1) ----------------
__global__ void __launch_bounds__(NF) logp_kernel(const float* __restrict__ w) {
    int p = blockIdx.x, t = threadIdx.x;
    int warp = t >> 5, lane = t & 31;
    __shared__ float red[16];
    __shared__ float bc;

    float v = w[p * NF + t];

    float m = v;
    #pragma unroll
    for (int o = 16; o; o >>= 1) m = fmaxf(m, __shfl_xor_sync(0xffffffffu, m, o));
    if (lane == 0) red[warp] = m;
    __syncthreads();
    if (warp == 0) {
        float t2 = red[lane & 15];
        #pragma unroll
        for (int o = 8; o; o >>= 1) t2 = fmaxf(t2, __shfl_xor_sync(0xffffffffu, t2, o));
        if (lane == 0) bc = t2;
    }
    __syncthreads();
    float mx = bc;
    __syncthreads();

    float sh = v - mx;
    float s = expf(sh);
    #pragma unroll
    for (int o = 16; o; o >>= 1) s += __shfl_xor_sync(0xffffffffu, s, o);
    if (lane == 0) red[warp] = s;
    __syncthreads();
    if (warp == 0) {
        float t2 = (lane < 16) ? red[lane] : 0.0f;
        #pragma unroll
        for (int o = 8; o; o >>= 1) t2 += __shfl_xor_sync(0xffffffffu, t2, o);
        if (lane == 0) bc = t2;
    }
    __syncthreads();
    g_logp[p * NF + t] = sh - logf(bc);
}

// ---------------- kernel B: fused sample + top-32 select + write ----------------
__global__ void __launch_bounds__(TPB) patch_kernel(const float* __restrict__ x,
                                                    const int* __restrict__ seedp,
                                                    float* __restrict__ out) {
    const int r   = blockIdx.x;
    const int tid = threadIdx.x;
    const int p   = r & (NP - 1);
    const int b   = r >> 6;
    const int f0  = tid * EPT;

    const uint32_t seed  = (uint32_t)seedp[0];
    const uint32_t cbase = (uint32_t)(r * NF + f0);

    // issue x load early to overlap with compute
    const float4 xv4 = *(const float4*)&x[b * NF + f0];

    uint32_t bits[EPT];
    #pragma unroll
    for (int e = 0; e < EPT; e++) {
        uint32_t o0, o1;
        threefry2x32(0u, seed, 0u, cbase + (uint32_t)e, o0, o1);
        bits[e] = o0 ^ o1;
    }

    const float4 lp4 = *(const float4*)&g_logp[p * NF + f0];
    const float  lps[EPT] = {lp4.x, lp4.y, lp4.z, lp4.w};

    float a[EPT];
    #pragma unroll
    for (int e = 0; e < EPT; e++)
        a[e] = approx_score(bits[e], lps[e]);

    __shared__ int                hist[256];
    __shared__ int                nIn_s, nb_s;
    __shared__ unsigned long long bval[NF];
    __shared__ unsigned char      sel[NF];

    if (tid == 0) { nIn_s = 0; nb_s = 0; }
    hist[tid] = 0;
    hist[tid + TPB] = 0;
    __syncthreads();

    // ONE linear histogram pass: bin = clamp(floor(8*a + 128), 0, 255)
    // scores provably in (-17, 14) for this problem; clamp is defensive only
    #pragma unroll
    for (int e = 0; e < EPT; e++) {
        int bi = __float2int_rd(fmaf(a[e], 8.0f, 128.0f));
        bi = max(0, min(255, bi));
        atomicAdd(&hist[bi], 1);
    }
    __syncthreads();

    // ALL warps redundantly suffix-scan the 256 bins (8 per lane) and find
    // the bin of the 32nd-largest; warp-broadcast via reduce_max. No barrier.
    int bin;
    {
        const int lane = tid & 31;
        const int base = lane * 8;
        int vals[8], suf[8];
        #pragma unroll
        for (int j = 0; j < 8; j++) vals[j] = hist[base + j];
        int acc = 0;
        #pragma unroll
        for (int j = 7; j >= 0; j--) { acc += vals[j]; suf[j] = acc; }
        int s = acc;
        #pragma unroll
        for (int o = 1; o < 32; o <<= 1) {
            int t = __shfl_down_sync(0xffffffffu, s, o);
            if (lane + o < 32) s += t;
        }
        const int above = s - acc;
        int myb = -1;
        #pragma unroll
        for (int j = 0; j < 8; j++) {
            int S     = suf[j] + above;                    // count >= this bin
            int Snext = (j < 7 ? suf[j + 1] : 0) + above;  // count >  this bin
            if (S >= PL && Snext < PL) myb = base + j;
        }
        bin = __reduce_max_sync(0xffffffffu, myb);         // exactly one lane found it
    }

    const float lo_edge = (float)(bin - 128) * 0.125f;
    const float hi_edge = lo_edge + 0.125f;
    const float hiT = hi_edge + EPSB;   // a >  hiT -> definitely IN
    const float loT = lo_edge - EPSB;   // a <  loT -> definitely OUT

    *(uint32_t*)&sel[f0] = 0u;   // clear this thread's 4 selection flags

    int cin = 0;
    #pragma unroll
    for (int e = 0; e < EPT; e++) cin += (a[e] > hiT);
    {
        int wsum = __reduce_add_sync(0xffffffffu, cin);
        if ((tid & 31) == 0) atomicAdd(&nIn_s, wsum);
    }

    // band: recompute exact score, publish (key, index) packed for tie-exact pick
    #pragma unroll
    for (int e = 0; e < EPT; e++) {
        if (a[e] <= hiT && a[e] >= loT) {
            uint32_t kx = ford(exact_score(bits[e], lps[e]));
            int pos = atomicAdd(&nb_s, 1);
            bval[pos] = ((unsigned long long)kx << 9) | (unsigned long long)(511 - (f0 + e));
        }
    }
    __syncthreads();

    if (tid == 0) {
        const int slots = PL - nIn_s;     // >= 1, and band count >= slots
        const int nb = nb_s;
        for (int s = 0; s < slots; s++) {
            unsigned long long best = 0ull; int bj = 0;
            for (int j = 0; j < nb; j++)
                if (bval[j] > best) { best = bval[j]; bj = j; }
            bval[bj] = 0ull;
            sel[511 - (int)(best & 511ull)] = 1;
        }
    }
    __syncthreads();

    const float xs[EPT] = {xv4.x, xv4.y, xv4.z, xv4.w};

    float mout[EPT], xmout[EPT];
    #pragma unroll
    for (int e = 0; e < EPT; e++) {
        bool in_ = (a[e] > hiT) || sel[f0 + e];
        mout[e]  = in_ ? 1.0f : 0.0f;
        xmout[e] = xs[e] * mout[e];
    }

    const size_t o = (size_t)r * (2 * NF);
    *(float4*)&out[o + f0]      = make_float4(xmout[0], xmout[1], xmout[2], xmout[3]);
    *(float4*)&out[o + NF + f0] = make_float4(mout[0],  mout[1],  mout[2],  mout[3]);
}

extern "C" void kernel_launch(void* const* d_in, const int* in_sizes, int n_in,
                              void* d_out, int out_size) {
    const float* x = (const float*)d_in[0];
    const float* w = (const float*)d_in[1];
    const int* seed = (const int*)d_in[2];
    float* out = (float*)d_out;

    logp_kernel<<<NP, NF>>>(w);
    patch_kernel<<<NROWS, TPB>>>(x, seed, out);
}

// round 15
// speedup vs baseline: 1.0830x; 1.0830x over previous
#include <cuda_runtime.h>
#include <stdint.h>

// ProbabilisticPatching: Gumbel-top-k, exact JAX *partitionable* threefry stream
// x:[2048,512] f32, weights:[64,512] f32, rng_seed int -> out [2048,64,1024] f32
//
// element i: (o0,o1)=threefry2x32((0,seed),(0,i)); bits=o0^o1
// u = max(1e-20, ((bits>>9)|0x3F800000).f32 - 1 + 1e-20)
// exact score = log_softmax(w)[p,f] - logf(-logf(u)); top-32 per (b,p) row.
//
// Fast path: approx score a (|a-s| <= ~4.3e-5), ONE 256-bin LINEAR histogram
// over score space; elements outside bin +/- EPS are provably IN/OUT; the
// band recomputes the bit-exact reference score (incl. index tie-break).
// Lessons: R9/R10 threefry is a serial dep chain (keep SHF+LOP3); R12 don't
// cap regs; R14 redundant per-warp scan costs more than the barrier it saves
// -> single-warp scan + barrier (R13 structure, measured best).

#define BATCH   2048
#define NP      64
#define NF      512
#define PL      32
#define NROWS   (BATCH * NP)          // 131072
#define TPB     128                   // threads per block
#define EPT     4                     // elements per thread (NF / TPB)
#define EPSB    2e-4f                 // band half-width (> 2x approx error bound)

__device__ float g_logp[NP * NF];

// ---------------- threefry2x32 (20 rounds, Skein schedule) ----------------
__device__ __forceinline__ void tf_round(uint32_t& a, uint32_t& b, int r) {
    a += b;
    b = __funnelshift_l(b, b, r);   // rotl
    b ^= a;
}

__device__ __forceinline__ void threefry2x32(uint32_t k0, uint32_t k1,
                                             uint32_t c0, uint32_t c1,
                                             uint32_t& o0, uint32_t& o1) {
    uint32_t ks2 = k0 ^ k1 ^ 0x1BD11BDAu;
    uint32_t x0 = c0 + k0, x1 = c1 + k1;
    tf_round(x0, x1, 13); tf_round(x0, x1, 15); tf_round(x0, x1, 26); tf_round(x0, x1, 6);
    x0 += k1;  x1 += ks2 + 1u;
    tf_round(x0, x1, 17); tf_round(x0, x1, 29); tf_round(x0, x1, 16); tf_round(x0, x1, 24);
    x0 += ks2; x1 += k0 + 2u;
    tf_round(x0, x1, 13); tf_round(x0, x1, 15); tf_round(x0, x1, 26); tf_round(x0, x1, 6);
    x0 += k0;  x1 += k1 + 3u;
    tf_round(x0, x1, 17); tf_round(x0, x1, 29); tf_round(x0, x1, 16); tf_round(x0, x1, 24);
    x0 += k1;  x1 += ks2 + 4u;
    tf_round(x0, x1, 13); tf_round(x0, x1, 15); tf_round(x0, x1, 26); tf_round(x0, x1, 6);
    x0 += ks2; x1 += k0 + 5u;
    o0 = x0; o1 = x1;
}

// JAX uniform(minval=1e-20, maxval=1.0), f32 path (exact reference form)
__device__ __forceinline__ float bits_to_uniform(uint32_t b) {
    float f = __uint_as_float((b >> 9) | 0x3F800000u) - 1.0f; // [0,1)
    return fmaxf(f + 1e-20f, 1e-20f);
}

// order-preserving float -> uint (only used for band exact-key packing)
__device__ __forceinline__ uint32_t ford(float f) {
    uint32_t u = __float_as_uint(f);
    return (u & 0x80000000u) ? ~u : (u | 0x80000000u);
}

// approx score: lp - log(-log(u)), |err| <= ~4.3e-5 absolute; branchless
// NOTE: fmaxf(ff,1e-20f) == fmaxf(ff+1e-20f,1e-20f) bitwise: smallest nonzero
// ff is 2^-23 (half-ulp 7e-15 >> 1e-20), and ff=0 yields 1e-20 either way.
__device__ __forceinline__ float approx_score(uint32_t bits, float lp) {
    float ff = __uint_as_float((bits >> 9) | 0x3F800000u) - 1.0f;  // [0,1), exact
    float u  = fmaxf(ff, 1e-20f);
    // path 1: u in [0.875,1): inner = -log1p(d), d = ff-1 exact, deg-4 Taylor
    // truncation rel err <= |d|^4/6 = 4.1e-5 at d = -0.125
    float d = ff - 1.0f;
    float P = fmaf(d, 0.2f, -0.25f);
    P = fmaf(d, P,  1.0f/3.0f);
    P = fmaf(d, P, -0.5f);
    P = fmaf(d, P,  1.0f);
    float inner_hi = -d * P;
    // path 2: u < 0.875: |log u| >= 0.1335, MUFU relative error is fine
    float inner_lo = -__logf(u);
    float inner = (ff >= 0.875f) ? inner_hi : inner_lo;
    return lp - __logf(inner);
}

// exact score: bit-identical to the reference path (R3/R4)
__device__ __forceinline__ float exact_score(uint32_t bits, float lp) {
    return lp - logf(-logf(bits_to_uniform(bits)));
}

// ---------------- kernel A: logp = log_softmax(weights, axis=-1) ----------------
__global__ void __launch_bounds__(NF) logp_kernel(const float* __restrict__ w) {
    int p = blockIdx.x, t = threadIdx.x;
    int warp = t >> 5, lane = t & 31;
    __shared__ float red[16];
    __shared__ float bc;

    float v = w[p * NF + t];

    float m = v;
    #pragma unroll
    for (int o = 16; o; o >>= 1) m = fmaxf(m, __shfl_xor_sync(0xffffffffu, m, o));
    if (lane == 0) red[warp] = m;
    __syncthreads();
    if (warp == 0) {
        float t2 = red[lane & 15];
        #pragma unroll
        for (int o = 8; o; o >>= 1) t2 = fmaxf(t2, __shfl_xor_sync(0xffffffffu, t2, o));
        if (lane == 0) bc = t2;
    }
    __syncthreads();
    float mx = bc;
    __syncthreads();

    float sh = v - mx;
    float s = expf(sh);
    #pragma unroll
    for (int o = 16; o; o >>= 1) s += __shfl_xor_sync(0xffffffffu, s, o);
    if (lane == 0) red[warp] = s;
    __syncthreads();
    if (warp == 0) {
        float t2 = (lane < 16) ? red[lane] : 0.0f;
        #pragma unroll
        for (int o = 8; o; o >>= 1) t2 += __shfl_xor_sync(0xffffffffu, t2, o);
        if (lane == 0) bc = t2;
    }
    __syncthreads();
    g_logp[p * NF + t] = sh - logf(bc);
}

// ---------------- kernel B: fused sample + top-32 select + write ----------------
__global__ void __launch_bounds__(TPB) patch_kernel(const float* __restrict__ x,
                                                    const int* __restrict__ seedp,
                                                    float* __restrict__ out) {
    const int r   = blockIdx.x;
    const int tid = threadIdx.x;
    const int p   = r & (NP - 1);
    const int b   = r >> 6;
    const int f0  = tid * EPT;

    const uint32_t seed  = (uint32_t)seedp[0];
    const uint32_t cbase = (uint32_t)(r * NF + f0);

    // issue x load early to overlap with compute
    const float4 xv4 = *(const float4*)&x[b * NF + f0];

    uint32_t bits[EPT];
    #pragma unroll
    for (int e = 0; e < EPT; e++) {
        uint32_t o0, o1;
        threefry2x32(0u, seed, 0u, cbase + (uint32_t)e, o0, o1);
        bits[e] = o0 ^ o1;
    }

    const float4 lp4 = *(const float4*)&g_logp[p * NF + f0];
    const float  lps[EPT] = {lp4.x, lp4.y, lp4.z, lp4.w};

    float a[EPT];
    #pragma unroll
    for (int e = 0; e < EPT; e++)
        a[e] = approx_score(bits[e], lps[e]);

    __shared__ int                hist[256];
    __shared__ int                bin_s, nIn_s, nb_s;
    __shared__ unsigned long long bval[NF];
    __shared__ unsigned char      sel[NF];

    if (tid == 0) { nIn_s = 0; nb_s = 0; }
    hist[tid] = 0;
    hist[tid + TPB] = 0;
    __syncthreads();

    // ONE linear histogram pass: bin = clamp(floor(8*a + 128), 0, 255)
    // scores provably in (-17, 14) for this problem; clamp is defensive only
    #pragma unroll
    for (int e = 0; e < EPT; e++) {
        int bi = __float2int_rd(fmaf(a[e], 8.0f, 128.0f));
        bi = max(0, min(255, bi));
        atomicAdd(&hist[bi], 1);
    }
    __syncthreads();

    // warp 0: suffix-scan 256 bins (8 per lane) -> bin of the 32nd largest
    if (tid < 32) {
        const int lane = tid;
        const int base = lane * 8;
        int vals[8], suf[8];
        #pragma unroll
        for (int j = 0; j < 8; j++) vals[j] = hist[base + j];
        int acc = 0;
        #pragma unroll
        for (int j = 7; j >= 0; j--) { acc += vals[j]; suf[j] = acc; }
        int s = acc;
        #pragma unroll
        for (int o = 1; o < 32; o <<= 1) {
            int t = __shfl_down_sync(0xffffffffu, s, o);
            if (lane + o < 32) s += t;
        }
        const int above = s - acc;
        #pragma unroll
        for (int j = 0; j < 8; j++) {
            int S     = suf[j] + above;                    // count >= this bin
            int Snext = (j < 7 ? suf[j + 1] : 0) + above;  // count >  this bin
            if (S >= PL && Snext < PL) bin_s = base + j;
        }
    }
    __syncthreads();

    const int   bin     = bin_s;
    const float lo_edge = (float)(bin - 128) * 0.125f;
    const float hi_edge = lo_edge + 0.125f;
    const float hiT = hi_edge + EPSB;   // a >  hiT -> definitely IN
    const float loT = lo_edge - EPSB;   // a <  loT -> definitely OUT

    *(uint32_t*)&sel[f0] = 0u;   // clear this thread's 4 selection flags

    int cin = 0;
    #pragma unroll
    for (int e = 0; e < EPT; e++) cin += (a[e] > hiT);
    {
        int wsum = __reduce_add_sync(0xffffffffu, cin);
        if ((tid & 31) == 0) atomicAdd(&nIn_s, wsum);
    }

    // band: recompute exact score, publish (key, index) packed for tie-exact pick
    #pragma unroll
    for (int e = 0; e < EPT; e++) {
        if (a[e] <= hiT && a[e] >= loT) {
            uint32_t kx = ford(exact_score(bits[e], lps[e]));
            int pos = atomicAdd(&nb_s, 1);
            bval[pos] = ((unsigned long long)kx << 9) | (unsigned long long)(511 - (f0 + e));
        }
    }
    __syncthreads();

    if (tid == 0) {
        const int slots = PL - nIn_s;     // >= 1, and band count >= slots
        const int nb = nb_s;
        for (int s = 0; s < slots; s++) {
            unsigned long long best = 0ull; int bj = 0;
            for (int j = 0; j < nb; j++)
                if (bval[j] > best) { best = bval[j]; bj = j; }
            bval[bj] = 0ull;
            sel[511 - (int)(best & 511ull)] = 1;
        }
    }
    __syncthreads();

    const float xs[EPT] = {xv4.x, xv4.y, xv4.z, xv4.w};

    float mout[EPT], xmout[EPT];
    #pragma unroll
    for (int e = 0; e < EPT; e++) {
        bool in_ = (a[e] > hiT) || sel[f0 + e];
        mout[e]  = in_ ? 1.0f : 0.0f;
        xmout[e] = xs[e] * mout[e];
    }

    const size_t o = (size_t)r * (2 * NF);
    *(float4*)&out[o + f0]      = make_float4(xmout[0], xmout[1], xmout[2], xmout[3]);
    *(float4*)&out[o + NF + f0] = make_float4(mout[0],  mout[1],  mout[2],  mout[3]);
}

extern "C" void kernel_launch(void* const* d_in, const int* in_sizes, int n_in,
                              void* d_out, int out_size) {
    const float* x = (const float*)d_in[0];
    const float* w = (const float*)d_in[1];
    const int* seed = (const int*)d_in[2];
    float* out = (float*)d_out;

    logp_kernel<<<NP, NF>>>(w);
    patch_kernel<<<NROWS, TPB>>>(x, seed, out);
}